// round 10
// baseline (speedup 1.0000x reference)
#include <cuda_runtime.h>
#include <cuda_bf16.h>
#include <cstdint>

// Problem constants
#define BB 8
#define CC 64
#define HH 256
#define WW 256
#define HW 65536           // H*W
#define TILE 16
#define HALO 2
#define EXT 20             // TILE + 2*HALO
#define EXT2 400           // EXT*EXT
#define NT 512             // threads per CTA (16 warps -> 4 per SMSP)

typedef unsigned long long ull;

// ---------------- scratch (static device globals; no runtime allocation) ----
__device__ float d_y[BB * CC * HW];          // post-residual activation (134 MB)
__device__ float d_ca[BB * CC];              // channel attention
__device__ float d_spmean[BB * HW];          // spatial mean over channels
__device__ float d_spmax[BB * HW];           // spatial max over channels
__device__ float d_sa[BB * HW];              // spatial attention
__device__ float d_gsum[BB * CC];            // channel sums (for avg pool)
__device__ unsigned int d_gmax[BB * CC];     // channel max (encoded)
__device__ float d_gnsum[BB * 8];            // groupnorm sums
__device__ float d_gnsq[BB * 8];             // groupnorm sum of squares

// ---------------- helpers ---------------------------------------------------
__device__ __forceinline__ float silu_f(float v) {
    return __fdividef(v, 1.f + __expf(-v));
}

__device__ __forceinline__ unsigned fenc(float f) {
    unsigned u = __float_as_uint(f);
    return (u & 0x80000000u) ? ~u : (u | 0x80000000u);
}
__device__ __forceinline__ float fdec(unsigned u) {
    return (u & 0x80000000u) ? __uint_as_float(u ^ 0x80000000u)
                             : __uint_as_float(~u);
}

// packed f32x2 FMA (Blackwell): d = a * b + d
__device__ __forceinline__ void fma2(ull &d, ull a, ull b) {
    asm("fma.rn.f32x2 %0, %1, %2, %0;" : "+l"(d) : "l"(a), "l"(b));
}
__device__ __forceinline__ ull splat2(float v) {
    unsigned u = __float_as_uint(v);
    ull r;
    asm("mov.b64 %0, {%1, %2};" : "=l"(r) : "r"(u), "r"(u));
    return r;
}
__device__ __forceinline__ void unpack2(ull v, float &lo, float &hi) {
    unsigned a, b;
    asm("mov.b64 {%0, %1}, %2;" : "=r"(a), "=r"(b) : "l"(v));
    lo = __uint_as_float(a);
    hi = __uint_as_float(b);
}

// ---------------- kernel 0: init reduction buffers -------------------------
__global__ void k_init() {
    int t = threadIdx.x;
    if (t < BB * CC) { d_gsum[t] = 0.f; d_gmax[t] = 0u; }
    if (t < BB * 8)  { d_gnsum[t] = 0.f; d_gnsq[t] = 0.f; }
}

// ---------------- kernel 1: fused conv1 + dw(1/3/5) + pw + residual --------
// 512 threads; each thread owns (pixel, co-half). Smem layout (floats):
//   sXH   [64*400]   = 25600   (x ext tile, overwritten in place by h; then sY)
//   sW1T  [64*64]    = 4096    (conv1 weights, transposed [ci][co])
//   sWpT  [192*64]   = 12288   (pw weights, transposed [c3][o])
//   sDw2  [64*9], sDw3 [64*25], sDw1/sCb1/sBd1/sBd2/sBd3/sBpw [64] each
#define OFF_W1T 25600
#define OFF_WPT 29696
#define OFF_DW2 41984
#define OFF_DW3 42560
#define OFF_DW1 44160
#define OFF_CB1 44224
#define OFF_BD1 44288
#define OFF_BD2 44352
#define OFF_BD3 44416
#define OFF_BPW 44480
#define SMEM_FLOATS 44544
#define SMEM_BYTES (SMEM_FLOATS * 4)

__global__ void __launch_bounds__(NT, 1)
k_main(const float *__restrict__ x,
       const float *__restrict__ c1w, const float *__restrict__ c1b,
       const float *__restrict__ d1w, const float *__restrict__ d1b,
       const float *__restrict__ d2w, const float *__restrict__ d2b,
       const float *__restrict__ d3w, const float *__restrict__ d3b,
       const float *__restrict__ pww, const float *__restrict__ pwb) {
    extern __shared__ float smem[];
    float *sXH  = smem;
    float *sW1T = smem + OFF_W1T;
    float *sWpT = smem + OFF_WPT;
    float *sDw2 = smem + OFF_DW2;
    float *sDw3 = smem + OFF_DW3;
    float *sDw1 = smem + OFF_DW1;
    float *sCb1 = smem + OFF_CB1;
    float *sBd1 = smem + OFF_BD1;
    float *sBd2 = smem + OFF_BD2;
    float *sBd3 = smem + OFF_BD3;
    float *sBpw = smem + OFF_BPW;

    const int tid = threadIdx.x;
    const int tileX = blockIdx.x, tileY = blockIdx.y, b = blockIdx.z;
    const int x0 = tileX * TILE - HALO, y0 = tileY * TILE - HALO;
    const float *xbase = x + ((b << 6) << 16);

    // ---- phase 1: weights into smem AND bulk-stage x ext tile into smem ----
    for (int i = tid; i < 4096; i += NT) {
        int ci = i >> 6, co = i & 63;
        sW1T[i] = c1w[(co << 6) | ci];          // conv1_w[co][ci]
    }
    for (int i = tid; i < 12288; i += NT) {
        int c3 = i >> 6, o = i & 63;
        sWpT[i] = pww[o * 192 + c3];            // pw_w[o][c3]
    }
    for (int i = tid; i < 576;  i += NT) sDw2[i] = d2w[i];
    for (int i = tid; i < 1600; i += NT) sDw3[i] = d3w[i];
    if (tid < 64) {
        sDw1[tid] = d1w[tid]; sCb1[tid] = c1b[tid];
        sBd1[tid] = d1b[tid]; sBd2[tid] = d2b[tid];
        sBd3[tid] = d3b[tid]; sBpw[tid] = pwb[tid];
    }
#pragma unroll 4
    for (int i = tid; i < 64 * EXT2; i += NT) {
        int c = i / EXT2;
        int p = i - c * EXT2;
        int py = p / EXT, px = p - py * EXT;
        int gy = y0 + py, gx = x0 + px;
        float v = 0.f;
        if ((unsigned)gy < HH && (unsigned)gx < WW)
            v = xbase[(c << 16) + (gy << 8) + gx];
        sXH[i] = v;
    }
    __syncthreads();

    // ---- phase 2: h = silu(conv1(x)), IN PLACE; unit = (pixel, co-half) ----
    // 800 units over 512 threads. A column p is read only by its own two
    // threads (same warp pair), reads complete before writes in program
    // order -> in-place safe.
    for (int u = tid; u < 2 * EXT2; u += NT) {
        const int p = u >> 1, half = u & 1;
        const int cobase = half << 5;
        ull acc2[16];
#pragma unroll
        for (int j = 0; j < 16; j++) acc2[j] = 0ull;
#pragma unroll 1
        for (int ci = 0; ci < 64; ci += 4) {
            float x0v = sXH[(ci + 0) * EXT2 + p];
            float x1v = sXH[(ci + 1) * EXT2 + p];
            float x2v = sXH[(ci + 2) * EXT2 + p];
            float x3v = sXH[(ci + 3) * EXT2 + p];
            ull s0 = splat2(x0v), s1 = splat2(x1v);
            ull s2 = splat2(x2v), s3 = splat2(x3v);
            const ulonglong2 *w0 = (const ulonglong2 *)(sW1T + ((ci + 0) << 6) + cobase);
            const ulonglong2 *w1 = (const ulonglong2 *)(sW1T + ((ci + 1) << 6) + cobase);
            const ulonglong2 *w2 = (const ulonglong2 *)(sW1T + ((ci + 2) << 6) + cobase);
            const ulonglong2 *w3 = (const ulonglong2 *)(sW1T + ((ci + 3) << 6) + cobase);
#pragma unroll
            for (int k = 0; k < 8; k++) {
                ulonglong2 a = w0[k];
                fma2(acc2[2 * k], a.x, s0); fma2(acc2[2 * k + 1], a.y, s0);
                ulonglong2 bb = w1[k];
                fma2(acc2[2 * k], bb.x, s1); fma2(acc2[2 * k + 1], bb.y, s1);
                ulonglong2 cc = w2[k];
                fma2(acc2[2 * k], cc.x, s2); fma2(acc2[2 * k + 1], cc.y, s2);
                ulonglong2 dd = w3[k];
                fma2(acc2[2 * k], dd.x, s3); fma2(acc2[2 * k + 1], dd.y, s3);
            }
        }
#pragma unroll
        for (int j = 0; j < 16; j++) {
            float lo, hi;
            unpack2(acc2[j], lo, hi);
            int co = cobase + 2 * j;
            sXH[co * EXT2 + p]       = silu_f(lo + sCb1[co]);
            sXH[(co + 1) * EXT2 + p] = silu_f(hi + sCb1[co + 1]);
        }
    }
    __syncthreads();

    // ---- phase 3: dw convs + pw matmul; unit = (inner pixel, co-half) -----
    float *sH = sXH;
    const int p3 = tid >> 1, half = tid & 1;
    const int cobase = half << 5;
    const int ty = p3 >> 4, tx = p3 & 15;
    const int cIdx = (ty + HALO) * EXT + (tx + HALO);
    const int gy = tileY * TILE + ty, gx = tileX * TILE + tx;
    const int gpix = (gy << 8) | gx;

    ull acc2[16];
#pragma unroll
    for (int j = 0; j < 16; j++) acc2[j] = 0ull;

#pragma unroll 1
    for (int c = 0; c < 64; c++) {
        const float *hb = sH + c * EXT2;
        float center = hb[cIdx];
        float h1v = fmaf(sDw1[c], center, sBd1[c]);

        // 3x3 depthwise: 2 partial chains
        const float *w2 = sDw2 + c * 9;
        float a2 = sBd2[c], b2 = 0.f;
        a2 = fmaf(w2[0], hb[cIdx - EXT - 1], a2);
        b2 = fmaf(w2[1], hb[cIdx - EXT    ], b2);
        a2 = fmaf(w2[2], hb[cIdx - EXT + 1], a2);
        b2 = fmaf(w2[3], hb[cIdx - 1], b2);
        a2 = fmaf(w2[4], center, a2);
        b2 = fmaf(w2[5], hb[cIdx + 1], b2);
        a2 = fmaf(w2[6], hb[cIdx + EXT - 1], a2);
        b2 = fmaf(w2[7], hb[cIdx + EXT    ], b2);
        a2 = fmaf(w2[8], hb[cIdx + EXT + 1], a2);
        float h2v = a2 + b2;

        // 5x5 depthwise: 3 partial chains
        const float *w3 = sDw3 + c * 25;
        float a3 = sBd3[c], b3 = 0.f, c3v = 0.f;
#pragma unroll
        for (int dy = -2; dy <= 2; dy++) {
            int rb = (dy + 2) * 5;
            int hbIdx = cIdx + dy * EXT;
            a3  = fmaf(w3[rb + 0], hb[hbIdx - 2], a3);
            b3  = fmaf(w3[rb + 1], hb[hbIdx - 1], b3);
            c3v = fmaf(w3[rb + 2], hb[hbIdx    ], c3v);
            a3  = fmaf(w3[rb + 3], hb[hbIdx + 1], a3);
            b3  = fmaf(w3[rb + 4], hb[hbIdx + 2], b3);
        }
        float h3v = (a3 + b3) + c3v;

        ull s1 = splat2(h1v), s2 = splat2(h2v), s3 = splat2(h3v);
        const ulonglong2 *r1 = (const ulonglong2 *)(sWpT + (c << 6) + cobase);
        const ulonglong2 *r2 = (const ulonglong2 *)(sWpT + ((64 + c) << 6) + cobase);
        const ulonglong2 *r3 = (const ulonglong2 *)(sWpT + ((128 + c) << 6) + cobase);
#pragma unroll
        for (int k = 0; k < 8; k++) {
            ulonglong2 a = r1[k];
            fma2(acc2[2 * k], a.x, s1); fma2(acc2[2 * k + 1], a.y, s1);
            ulonglong2 bb = r2[k];
            fma2(acc2[2 * k], bb.x, s2); fma2(acc2[2 * k + 1], bb.y, s2);
            ulonglong2 cc = r3[k];
            fma2(acc2[2 * k], cc.x, s3); fma2(acc2[2 * k + 1], cc.y, s3);
        }
    }

    __syncthreads();            // all sH reads done; reuse as sY
    float *sY = sH;             // alias: [256 pixels][stride 65]

    const float *xr = x + ((b << 6) << 16) + gpix;
#pragma unroll
    for (int j = 0; j < 16; j++) {
        float lo, hi;
        unpack2(acc2[j], lo, hi);
        int c0 = cobase + 2 * j;
        {
            float t = silu_f(lo + sBpw[c0]);
            float r = t + xr[c0 << 16];
            float y0v = silu_f(r);
            d_y[(((b << 6) | c0) << 16) + gpix] = y0v;
            sY[p3 * 65 + c0] = y0v;
        }
        {
            int c1 = c0 + 1;
            float t = silu_f(hi + sBpw[c1]);
            float r = t + xr[c1 << 16];
            float y1v = silu_f(r);
            d_y[(((b << 6) | c1) << 16) + gpix] = y1v;
            sY[p3 * 65 + c1] = y1v;
        }
    }
    __syncthreads();

    // ---- per-(b,c) block reduction for channel attention ----
    if (tid < 64) {
        float s = 0.f, m = -3e38f;
#pragma unroll 4
        for (int p = 0; p < 256; p++) {
            float v = sY[p * 65 + tid];
            s += v;
            m = fmaxf(m, v);
        }
        atomicAdd(&d_gsum[(b << 6) | tid], s);
        atomicMax(&d_gmax[(b << 6) | tid], fenc(m));
    }
}

// ---------------- kernel 2: channel attention MLP --------------------------
__global__ void k_ca(const float *__restrict__ caw1, const float *__restrict__ caw2) {
    int b = blockIdx.x, c = threadIdx.x;
    __shared__ float pa[64], pm[64], ha[8], hm[8];
    pa[c] = d_gsum[(b << 6) | c] * (1.f / 65536.f);
    pm[c] = fdec(d_gmax[(b << 6) | c]);
    __syncthreads();
    if (c < 8) {
        float sa_ = 0.f, sm_ = 0.f;
#pragma unroll
        for (int i = 0; i < 64; i++) {
            float w = caw1[c * 64 + i];
            sa_ += w * pa[i];
            sm_ += w * pm[i];
        }
        ha[c] = fmaxf(sa_, 0.f);
        hm[c] = fmaxf(sm_, 0.f);
    }
    __syncthreads();
    float oa = 0.f, om = 0.f;
#pragma unroll
    for (int j = 0; j < 8; j++) {
        float w = caw2[c * 8 + j];
        oa += w * ha[j];
        om += w * hm[j];
    }
    d_ca[(b << 6) | c] = silu_f(oa + om);
}

// ---------------- kernel 3: spatial mean/max over channels -----------------
__global__ void k_sp() {
    int b = blockIdx.x >> 8;
    int y = blockIdx.x & 255;
    int xx = threadIdx.x;
    int p = (y << 8) | xx;
    const float *yb = d_y + ((b << 6) << 16) + p;
    const float *cab = d_ca + (b << 6);
    float s = 0.f, m = -3e38f;
#pragma unroll 8
    for (int c = 0; c < 64; c++) {
        float v = cab[c] * yb[c << 16];
        s += v;
        m = fmaxf(m, v);
    }
    d_spmean[(b << 16) | p] = s * (1.f / 64.f);
    d_spmax[(b << 16) | p] = m;
}

// ---------------- kernel 4: spatial attention 7x7 conv ---------------------
__global__ void k_sa(const float *__restrict__ saw, const float *__restrict__ sab) {
    __shared__ float sm[2][22][22];
    __shared__ float sw[98];
    int tx = threadIdx.x, ty = threadIdx.y;
    int tid = ty * 16 + tx;
    int b = blockIdx.z;
    int gx0 = blockIdx.x * 16 - 3, gy0 = blockIdx.y * 16 - 3;
    if (tid < 98) sw[tid] = saw[tid];
    for (int i = tid; i < 2 * 22 * 22; i += 256) {
        int ch = i / 484;
        int r = i - ch * 484;
        int py = r / 22, px = r - py * 22;
        int gy = gy0 + py, gx = gx0 + px;
        float v = 0.f;
        if ((unsigned)gy < HH && (unsigned)gx < WW)
            v = (ch ? d_spmax : d_spmean)[(b << 16) + (gy << 8) + gx];
        sm[ch][py][px] = v;
    }
    __syncthreads();
    float acc = sab[0];
#pragma unroll
    for (int ch = 0; ch < 2; ch++)
#pragma unroll
        for (int dy = 0; dy < 7; dy++)
#pragma unroll
            for (int dx = 0; dx < 7; dx++)
                acc = fmaf(sw[ch * 49 + dy * 7 + dx], sm[ch][ty + dy][tx + dx], acc);
    int gy = blockIdx.y * 16 + ty, gx = blockIdx.x * 16 + tx;
    d_sa[(b << 16) + (gy << 8) + gx] = silu_f(acc);
}

// ---------------- kernel 5: groupnorm statistics ---------------------------
__global__ void k_gnstats() {
    int chunk = blockIdx.x, c = blockIdx.y, b = blockIdx.z;
    int tid = threadIdx.x;
    float cav = d_ca[(b << 6) | c];
    const float *yb = d_y + (((b << 6) | c) << 16);
    const float *sab = d_sa + (b << 16);
    int base = chunk * 4096;
    float s = 0.f, sq = 0.f;
#pragma unroll
    for (int i = 0; i < 16; i++) {
        int p = base + (i << 8) + tid;
        float v = sab[p] * cav * yb[p];
        s += v;
        sq += v * v;
    }
#pragma unroll
    for (int o = 16; o; o >>= 1) {
        s  += __shfl_xor_sync(0xFFFFFFFFu, s, o);
        sq += __shfl_xor_sync(0xFFFFFFFFu, sq, o);
    }
    __shared__ float ws[8], wq[8];
    int w = tid >> 5, l = tid & 31;
    if (!l) { ws[w] = s; wq[w] = sq; }
    __syncthreads();
    if (tid == 0) {
        float S = 0.f, Q = 0.f;
#pragma unroll
        for (int i = 0; i < 8; i++) { S += ws[i]; Q += wq[i]; }
        atomicAdd(&d_gnsum[(b << 3) | (c >> 3)], S);
        atomicAdd(&d_gnsq[(b << 3) | (c >> 3)], Q);
    }
}

// ---------------- kernel 6: groupnorm apply + silu -> out ------------------
__global__ void k_fin(float *__restrict__ out,
                      const float *__restrict__ gng, const float *__restrict__ gnb) {
    int chunk = blockIdx.x, c = blockIdx.y, b = blockIdx.z;
    int tid = threadIdx.x;
    float cav = d_ca[(b << 6) | c];
    int gi = (b << 3) | (c >> 3);
    const float Ninv = 1.f / 524288.f;   // 8 channels * 65536 pixels
    float mu = d_gnsum[gi] * Ninv;
    float var = d_gnsq[gi] * Ninv - mu * mu;
    float inv = rsqrtf(var + 1e-5f);
    float ga = gng[c], be = gnb[c];
    int coff = ((b << 6) | c) << 16;
    const float *yb = d_y + coff;
    const float *sab = d_sa + (b << 16);
    float *ob = out + coff;
    int base = chunk * 4096;
#pragma unroll
    for (int i = 0; i < 16; i++) {
        int p = base + (i << 8) + tid;
        float v = sab[p] * cav * yb[p];
        float g = (v - mu) * inv * ga + be;
        ob[p] = silu_f(g);
    }
}

// ---------------- launch ----------------------------------------------------
extern "C" void kernel_launch(void *const *d_in, const int *in_sizes, int n_in,
                              void *d_out, int out_size) {
    const float *x      = (const float *)d_in[0];
    const float *c1w    = (const float *)d_in[1];
    const float *c1b    = (const float *)d_in[2];
    const float *d1w    = (const float *)d_in[3];
    const float *d1b    = (const float *)d_in[4];
    const float *d2w    = (const float *)d_in[5];
    const float *d2b    = (const float *)d_in[6];
    const float *d3w    = (const float *)d_in[7];
    const float *d3b    = (const float *)d_in[8];
    const float *pww    = (const float *)d_in[9];
    const float *pwb    = (const float *)d_in[10];
    const float *caw1   = (const float *)d_in[11];
    const float *caw2   = (const float *)d_in[12];
    const float *saw    = (const float *)d_in[13];
    const float *sab    = (const float *)d_in[14];
    const float *gng    = (const float *)d_in[15];
    const float *gnb    = (const float *)d_in[16];

    cudaFuncSetAttribute(k_main, cudaFuncAttributeMaxDynamicSharedMemorySize,
                         SMEM_BYTES);

    k_init<<<1, 512>>>();
    k_main<<<dim3(16, 16, 8), NT, SMEM_BYTES>>>(
        x, c1w, c1b, d1w, d1b, d2w, d2b, d3w, d3b, pww, pwb);
    k_ca<<<8, 64>>>(caw1, caw2);
    k_sp<<<BB * HH, 256>>>();
    k_sa<<<dim3(16, 16, 8), dim3(16, 16)>>>(saw, sab);
    k_gnstats<<<dim3(16, 64, 8), 256>>>();
    k_fin<<<dim3(16, 64, 8), 256>>>((float *)d_out, gng, gnb);
}

// round 12
// speedup vs baseline: 1.3634x; 1.3634x over previous
#include <cuda_runtime.h>
#include <cuda_bf16.h>
#include <cstdint>

// Problem constants
#define BB 8
#define CC 64
#define HH 256
#define WW 256
#define HW 65536
#define TILE 16
#define HALO 2
#define EXT 20
#define EXT2 400
#define NT 256

typedef unsigned long long ull;

// ---------------- scratch ----------------------------------------------------
__device__ float d_y[BB * CC * HW];
__device__ float d_ca[BB * CC];
__device__ float d_spmean[BB * HW];
__device__ float d_spmax[BB * HW];
__device__ float d_sa[BB * HW];
__device__ float d_gsum[BB * CC];
__device__ unsigned int d_gmax[BB * CC];
__device__ float d_gnsum[BB * 8];
__device__ float d_gnsq[BB * 8];

// ---------------- helpers ---------------------------------------------------
__device__ __forceinline__ float silu_f(float v) {
    return __fdividef(v, 1.f + __expf(-v));
}
__device__ __forceinline__ unsigned fenc(float f) {
    unsigned u = __float_as_uint(f);
    return (u & 0x80000000u) ? ~u : (u | 0x80000000u);
}
__device__ __forceinline__ float fdec(unsigned u) {
    return (u & 0x80000000u) ? __uint_as_float(u ^ 0x80000000u)
                             : __uint_as_float(~u);
}
__device__ __forceinline__ void fma2(ull &d, ull a, ull b) {
    asm("fma.rn.f32x2 %0, %1, %2, %0;" : "+l"(d) : "l"(a), "l"(b));
}
__device__ __forceinline__ ull splat2(float v) {
    unsigned u = __float_as_uint(v);
    ull r;
    asm("mov.b64 %0, {%1, %2};" : "=l"(r) : "r"(u), "r"(u));
    return r;
}
__device__ __forceinline__ void unpack2(ull v, float &lo, float &hi) {
    unsigned a, b;
    asm("mov.b64 {%0, %1}, %2;" : "=r"(a), "=r"(b) : "l"(v));
    lo = __uint_as_float(a);
    hi = __uint_as_float(b);
}

// ---------------- kernel 0 + profiling alignment nops ----------------------
__global__ void k_init() {
    int t = threadIdx.x;
    if (t < BB * CC) { d_gsum[t] = 0.f; d_gmax[t] = 0u; }
    if (t < BB * 8)  { d_gnsum[t] = 0.f; d_gnsq[t] = 0.f; }
}
__global__ void k_nop1() {}
__global__ void k_nop2() {}
__global__ void k_nop3() {}
__global__ void k_nop4() {}

// ---------------- kernel 1: fused block --------------------------------------
// smem layout (floats)
#define OFF_W1T 25600            // conv1 weights [ci][co]        4096
#define OFF_WPT 29696            // pw weights [c3][o]           12288
#define OFF_HC  41984            // h123 chunk [24][256]          6144
#define OFF_DW2 48128            // 576
#define OFF_DW3 48704            // 1600
#define OFF_DW1 50304
#define OFF_CB1 50368
#define OFF_BD1 50432
#define OFF_BD2 50496
#define OFF_BD3 50560
#define OFF_BPW 50624
#define SMEM_FLOATS 50688
#define SMEM_BYTES (SMEM_FLOATS * 4)

// conv1: one unit = (pixel-quad pq, co-group cog of 16). acc[j*8+kp] (j=px, kp=co-pair)
__device__ __forceinline__ void conv1_unit(const float *sXH, const float *sW1T,
                                           int u, ull *acc) {
    const int pq = u >> 2, cog = u & 3;
    const int col0 = pq << 2;
#pragma unroll
    for (int j = 0; j < 32; j++) acc[j] = 0ull;
#pragma unroll 2
    for (int ci = 0; ci < 64; ci++) {
        float4 xv = *(const float4 *)(sXH + ci * EXT2 + col0);
        const ulonglong2 *wp = (const ulonglong2 *)(sW1T + (ci << 6) + (cog << 4));
        ulonglong2 W0 = wp[0], W1 = wp[1], W2 = wp[2], W3 = wp[3];
        ull s;
        s = splat2(xv.x);
        fma2(acc[0], W0.x, s); fma2(acc[1], W0.y, s);
        fma2(acc[2], W1.x, s); fma2(acc[3], W1.y, s);
        fma2(acc[4], W2.x, s); fma2(acc[5], W2.y, s);
        fma2(acc[6], W3.x, s); fma2(acc[7], W3.y, s);
        s = splat2(xv.y);
        fma2(acc[8],  W0.x, s); fma2(acc[9],  W0.y, s);
        fma2(acc[10], W1.x, s); fma2(acc[11], W1.y, s);
        fma2(acc[12], W2.x, s); fma2(acc[13], W2.y, s);
        fma2(acc[14], W3.x, s); fma2(acc[15], W3.y, s);
        s = splat2(xv.z);
        fma2(acc[16], W0.x, s); fma2(acc[17], W0.y, s);
        fma2(acc[18], W1.x, s); fma2(acc[19], W1.y, s);
        fma2(acc[20], W2.x, s); fma2(acc[21], W2.y, s);
        fma2(acc[22], W3.x, s); fma2(acc[23], W3.y, s);
        s = splat2(xv.w);
        fma2(acc[24], W0.x, s); fma2(acc[25], W0.y, s);
        fma2(acc[26], W1.x, s); fma2(acc[27], W1.y, s);
        fma2(acc[28], W2.x, s); fma2(acc[29], W2.y, s);
        fma2(acc[30], W3.x, s); fma2(acc[31], W3.y, s);
    }
}

__device__ __forceinline__ void conv1_write(float *sXH, const float *sCb1,
                                            int u, ull *acc) {
    const int pq = u >> 2, cog = u & 3;
    const int col0 = pq << 2;
#pragma unroll
    for (int j = 0; j < 4; j++)
#pragma unroll
        for (int kp = 0; kp < 8; kp++) {
            float lo, hi;
            unpack2(acc[j * 8 + kp], lo, hi);
            int co = (cog << 4) + 2 * kp;
            sXH[co * EXT2 + col0 + j]       = silu_f(lo + sCb1[co]);
            sXH[(co + 1) * EXT2 + col0 + j] = silu_f(hi + sCb1[co + 1]);
        }
}

__global__ void __launch_bounds__(NT, 1)
k_main(const float *__restrict__ x,
       const float *__restrict__ c1w, const float *__restrict__ c1b,
       const float *__restrict__ d1w, const float *__restrict__ d1b,
       const float *__restrict__ d2w, const float *__restrict__ d2b,
       const float *__restrict__ d3w, const float *__restrict__ d3b,
       const float *__restrict__ pww, const float *__restrict__ pwb) {
    extern __shared__ float smem[];
    float *sXH  = smem;
    float *sW1T = smem + OFF_W1T;
    float *sWpT = smem + OFF_WPT;
    float *sHC  = smem + OFF_HC;
    float *sDw2 = smem + OFF_DW2;
    float *sDw3 = smem + OFF_DW3;
    float *sDw1 = smem + OFF_DW1;
    float *sCb1 = smem + OFF_CB1;
    float *sBd1 = smem + OFF_BD1;
    float *sBd2 = smem + OFF_BD2;
    float *sBd3 = smem + OFF_BD3;
    float *sBpw = smem + OFF_BPW;

    const int tid = threadIdx.x;
    const int tileX = blockIdx.x, tileY = blockIdx.y, b = blockIdx.z;
    const int x0 = tileX * TILE - HALO, y0 = tileY * TILE - HALO;
    const float *xbase = x + ((b << 6) << 16);

    // ---- phase 1: weights into smem + bulk-stage x ext tile ----
    for (int i = tid; i < 4096; i += NT) {
        int ci = i >> 6, co = i & 63;
        sW1T[i] = c1w[(co << 6) | ci];
    }
    for (int i = tid; i < 12288; i += NT) {
        int c3 = i >> 6, o = i & 63;
        sWpT[i] = pww[o * 192 + c3];
    }
    for (int i = tid; i < 576;  i += NT) sDw2[i] = d2w[i];
    for (int i = tid; i < 1600; i += NT) sDw3[i] = d3w[i];
    if (tid < 64) {
        sDw1[tid] = d1w[tid]; sCb1[tid] = c1b[tid];
        sBd1[tid] = d1b[tid]; sBd2[tid] = d2b[tid];
        sBd3[tid] = d3b[tid]; sBpw[tid] = pwb[tid];
    }
#pragma unroll 4
    for (int i = tid; i < 64 * EXT2; i += NT) {
        int c = i / EXT2;
        int p = i - c * EXT2;
        int py = p / EXT, px = p - py * EXT;
        int gy = y0 + py, gx = x0 + px;
        float v = 0.f;
        if ((unsigned)gy < HH && (unsigned)gx < WW)
            v = xbase[(c << 16) + (gy << 8) + gx];
        sXH[i] = v;
    }
    __syncthreads();

    // ---- phase 2: h = silu(conv1(x)) in place, two staged waves ----
    // wave A: units 0..255 (columns 0..255); wave B: units 256..399 (cols 256..399)
    {
        ull acc[32];
        conv1_unit(sXH, sW1T, tid, acc);       // reads cols 0..255 only
        __syncthreads();                       // all A-reads done
        conv1_write(sXH, sCb1, tid, acc);      // writes cols 0..255
        if (tid < 144)
            conv1_unit(sXH, sW1T, 256 + tid, acc);  // reads cols 256..399 (untouched)
        __syncthreads();                       // all B-reads done
        if (tid < 144)
            conv1_write(sXH, sCb1, 256 + tid, acc);
        __syncthreads();
    }

    // ---- phase 3: chunked dw + pw GEMM ----
    float *sH = sXH;
    const int pq = tid >> 2, cog = tid & 3;
    const int col0 = pq << 2;
    // dw per-pixel indices (px = tid)
    const int dty = tid >> 4, dtx = tid & 15;
    const int dIdx = (dty + HALO) * EXT + (dtx + HALO);

    ull acc[32];
#pragma unroll
    for (int j = 0; j < 32; j++) acc[j] = 0ull;

#pragma unroll 1
    for (int cc = 0; cc < 8; cc++) {
        const int c0 = cc << 3;
        // dw-pass: each thread computes h1/h2/h3 for pixel=tid, channels c0..c0+7
#pragma unroll
        for (int i = 0; i < 8; i++) {
            const int c = c0 + i;
            const float *hb = sH + c * EXT2;
            float center = hb[dIdx];
            float h1v = fmaf(sDw1[c], center, sBd1[c]);

            const float *w2 = sDw2 + c * 9;
            float a2 = sBd2[c], b2 = 0.f;
            a2 = fmaf(w2[0], hb[dIdx - EXT - 1], a2);
            b2 = fmaf(w2[1], hb[dIdx - EXT    ], b2);
            a2 = fmaf(w2[2], hb[dIdx - EXT + 1], a2);
            b2 = fmaf(w2[3], hb[dIdx - 1], b2);
            a2 = fmaf(w2[4], center, a2);
            b2 = fmaf(w2[5], hb[dIdx + 1], b2);
            a2 = fmaf(w2[6], hb[dIdx + EXT - 1], a2);
            b2 = fmaf(w2[7], hb[dIdx + EXT    ], b2);
            a2 = fmaf(w2[8], hb[dIdx + EXT + 1], a2);
            float h2v = a2 + b2;

            const float *w3 = sDw3 + c * 25;
            float a3 = sBd3[c], b3 = 0.f, c3v = 0.f;
#pragma unroll
            for (int dy = -2; dy <= 2; dy++) {
                int rb = (dy + 2) * 5;
                int hbIdx = dIdx + dy * EXT;
                a3  = fmaf(w3[rb + 0], hb[hbIdx - 2], a3);
                b3  = fmaf(w3[rb + 1], hb[hbIdx - 1], b3);
                c3v = fmaf(w3[rb + 2], hb[hbIdx    ], c3v);
                a3  = fmaf(w3[rb + 3], hb[hbIdx + 1], a3);
                b3  = fmaf(w3[rb + 4], hb[hbIdx + 2], b3);
            }
            float h3v = (a3 + b3) + c3v;

            sHC[(0 * 8 + i) * 256 + tid] = h1v;
            sHC[(1 * 8 + i) * 256 + tid] = h2v;
            sHC[(2 * 8 + i) * 256 + tid] = h3v;
        }
        __syncthreads();
        // GEMM accumulate over 24 k-rows of this chunk
#pragma unroll
        for (int t = 0; t < 3; t++)
#pragma unroll
            for (int i = 0; i < 8; i++) {
                const int krow = t * 64 + c0 + i;
                float4 hv = *(const float4 *)(sHC + (t * 8 + i) * 256 + col0);
                const ulonglong2 *wp =
                    (const ulonglong2 *)(sWpT + (krow << 6) + (cog << 4));
                ulonglong2 W0 = wp[0], W1 = wp[1], W2 = wp[2], W3 = wp[3];
                ull s;
                s = splat2(hv.x);
                fma2(acc[0], W0.x, s); fma2(acc[1], W0.y, s);
                fma2(acc[2], W1.x, s); fma2(acc[3], W1.y, s);
                fma2(acc[4], W2.x, s); fma2(acc[5], W2.y, s);
                fma2(acc[6], W3.x, s); fma2(acc[7], W3.y, s);
                s = splat2(hv.y);
                fma2(acc[8],  W0.x, s); fma2(acc[9],  W0.y, s);
                fma2(acc[10], W1.x, s); fma2(acc[11], W1.y, s);
                fma2(acc[12], W2.x, s); fma2(acc[13], W2.y, s);
                fma2(acc[14], W3.x, s); fma2(acc[15], W3.y, s);
                s = splat2(hv.z);
                fma2(acc[16], W0.x, s); fma2(acc[17], W0.y, s);
                fma2(acc[18], W1.x, s); fma2(acc[19], W1.y, s);
                fma2(acc[20], W2.x, s); fma2(acc[21], W2.y, s);
                fma2(acc[22], W3.x, s); fma2(acc[23], W3.y, s);
                s = splat2(hv.w);
                fma2(acc[24], W0.x, s); fma2(acc[25], W0.y, s);
                fma2(acc[26], W1.x, s); fma2(acc[27], W1.y, s);
                fma2(acc[28], W2.x, s); fma2(acc[29], W2.y, s);
                fma2(acc[30], W3.x, s); fma2(acc[31], W3.y, s);
            }
        __syncthreads();   // sHC reused next chunk
    }

    // ---- epilogue: t = silu(pw + bias) -> sY; then coalesced residual pass ----
    float *sY = sH;   // [256 px][stride 65]; sH fully consumed by dw-passes
#pragma unroll
    for (int j = 0; j < 4; j++) {
        int px = col0 + j;
#pragma unroll
        for (int kp = 0; kp < 8; kp++) {
            float lo, hi;
            unpack2(acc[j * 8 + kp], lo, hi);
            int co = (cog << 4) + 2 * kp;
            sY[px * 65 + co]     = silu_f(lo + sBpw[co]);
            sY[px * 65 + co + 1] = silu_f(hi + sBpw[co + 1]);
        }
    }
    __syncthreads();

    {
        const int ty = tid >> 4, tx = tid & 15;
        const int gy = tileY * TILE + ty, gx = tileX * TILE + tx;
        const int gpix = (gy << 8) | gx;
        const float *xr = x + ((b << 6) << 16) + gpix;
        float *yb = d_y + ((b << 6) << 16) + gpix;
#pragma unroll 8
        for (int c = 0; c < 64; c++) {
            float t = sY[tid * 65 + c];
            float yv = silu_f(t + xr[c << 16]);
            yb[c << 16] = yv;
            sY[tid * 65 + c] = yv;
        }
    }
    __syncthreads();

    // ---- per-(b,c) block reduction for channel attention ----
    if (tid < 64) {
        float s = 0.f, m = -3e38f;
#pragma unroll 4
        for (int p = 0; p < 256; p++) {
            float v = sY[p * 65 + tid];
            s += v;
            m = fmaxf(m, v);
        }
        atomicAdd(&d_gsum[(b << 6) | tid], s);
        atomicMax(&d_gmax[(b << 6) | tid], fenc(m));
    }
}

// ---------------- kernel 2: channel attention MLP --------------------------
__global__ void k_ca(const float *__restrict__ caw1, const float *__restrict__ caw2) {
    int b = blockIdx.x, c = threadIdx.x;
    __shared__ float pa[64], pm[64], ha[8], hm[8];
    pa[c] = d_gsum[(b << 6) | c] * (1.f / 65536.f);
    pm[c] = fdec(d_gmax[(b << 6) | c]);
    __syncthreads();
    if (c < 8) {
        float sa_ = 0.f, sm_ = 0.f;
#pragma unroll
        for (int i = 0; i < 64; i++) {
            float w = caw1[c * 64 + i];
            sa_ += w * pa[i];
            sm_ += w * pm[i];
        }
        ha[c] = fmaxf(sa_, 0.f);
        hm[c] = fmaxf(sm_, 0.f);
    }
    __syncthreads();
    float oa = 0.f, om = 0.f;
#pragma unroll
    for (int j = 0; j < 8; j++) {
        float w = caw2[c * 8 + j];
        oa += w * ha[j];
        om += w * hm[j];
    }
    d_ca[(b << 6) | c] = silu_f(oa + om);
}

// ---------------- kernel 3: spatial mean/max over channels -----------------
__global__ void k_sp() {
    int b = blockIdx.x >> 8;
    int y = blockIdx.x & 255;
    int xx = threadIdx.x;
    int p = (y << 8) | xx;
    const float *yb = d_y + ((b << 6) << 16) + p;
    const float *cab = d_ca + (b << 6);
    float s = 0.f, m = -3e38f;
#pragma unroll 8
    for (int c = 0; c < 64; c++) {
        float v = cab[c] * yb[c << 16];
        s += v;
        m = fmaxf(m, v);
    }
    d_spmean[(b << 16) | p] = s * (1.f / 64.f);
    d_spmax[(b << 16) | p] = m;
}

// ---------------- kernel 4: spatial attention 7x7 conv ---------------------
__global__ void k_sa(const float *__restrict__ saw, const float *__restrict__ sab) {
    __shared__ float sm[2][22][22];
    __shared__ float sw[98];
    int tx = threadIdx.x, ty = threadIdx.y;
    int tid = ty * 16 + tx;
    int b = blockIdx.z;
    int gx0 = blockIdx.x * 16 - 3, gy0 = blockIdx.y * 16 - 3;
    if (tid < 98) sw[tid] = saw[tid];
    for (int i = tid; i < 2 * 22 * 22; i += 256) {
        int ch = i / 484;
        int r = i - ch * 484;
        int py = r / 22, px = r - py * 22;
        int gy = gy0 + py, gx = gx0 + px;
        float v = 0.f;
        if ((unsigned)gy < HH && (unsigned)gx < WW)
            v = (ch ? d_spmax : d_spmean)[(b << 16) + (gy << 8) + gx];
        sm[ch][py][px] = v;
    }
    __syncthreads();
    float acc = sab[0];
#pragma unroll
    for (int ch = 0; ch < 2; ch++)
#pragma unroll
        for (int dy = 0; dy < 7; dy++)
#pragma unroll
            for (int dx = 0; dx < 7; dx++)
                acc = fmaf(sw[ch * 49 + dy * 7 + dx], sm[ch][ty + dy][tx + dx], acc);
    int gy = blockIdx.y * 16 + ty, gx = blockIdx.x * 16 + tx;
    d_sa[(b << 16) + (gy << 8) + gx] = silu_f(acc);
}

// ---------------- kernel 5: groupnorm statistics ---------------------------
__global__ void k_gnstats() {
    int chunk = blockIdx.x, c = blockIdx.y, b = blockIdx.z;
    int tid = threadIdx.x;
    float cav = d_ca[(b << 6) | c];
    const float *yb = d_y + (((b << 6) | c) << 16);
    const float *sab = d_sa + (b << 16);
    int base = chunk * 4096;
    float s = 0.f, sq = 0.f;
#pragma unroll
    for (int i = 0; i < 16; i++) {
        int p = base + (i << 8) + tid;
        float v = sab[p] * cav * yb[p];
        s += v;
        sq += v * v;
    }
#pragma unroll
    for (int o = 16; o; o >>= 1) {
        s  += __shfl_xor_sync(0xFFFFFFFFu, s, o);
        sq += __shfl_xor_sync(0xFFFFFFFFu, sq, o);
    }
    __shared__ float ws[8], wq[8];
    int w = tid >> 5, l = tid & 31;
    if (!l) { ws[w] = s; wq[w] = sq; }
    __syncthreads();
    if (tid == 0) {
        float S = 0.f, Q = 0.f;
#pragma unroll
        for (int i = 0; i < 8; i++) { S += ws[i]; Q += wq[i]; }
        atomicAdd(&d_gnsum[(b << 3) | (c >> 3)], S);
        atomicAdd(&d_gnsq[(b << 3) | (c >> 3)], Q);
    }
}

// ---------------- kernel 6: groupnorm apply + silu -> out ------------------
__global__ void k_fin(float *__restrict__ out,
                      const float *__restrict__ gng, const float *__restrict__ gnb) {
    int chunk = blockIdx.x, c = blockIdx.y, b = blockIdx.z;
    int tid = threadIdx.x;
    float cav = d_ca[(b << 6) | c];
    int gi = (b << 3) | (c >> 3);
    const float Ninv = 1.f / 524288.f;
    float mu = d_gnsum[gi] * Ninv;
    float var = d_gnsq[gi] * Ninv - mu * mu;
    float inv = rsqrtf(var + 1e-5f);
    float ga = gng[c], be = gnb[c];
    int coff = ((b << 6) | c) << 16;
    const float *yb = d_y + coff;
    const float *sab = d_sa + (b << 16);
    float *ob = out + coff;
    int base = chunk * 4096;
#pragma unroll
    for (int i = 0; i < 16; i++) {
        int p = base + (i << 8) + tid;
        float v = sab[p] * cav * yb[p];
        float g = (v - mu) * inv * ga + be;
        ob[p] = silu_f(g);
    }
}

// ---------------- launch ----------------------------------------------------
extern "C" void kernel_launch(void *const *d_in, const int *in_sizes, int n_in,
                              void *d_out, int out_size) {
    const float *x      = (const float *)d_in[0];
    const float *c1w    = (const float *)d_in[1];
    const float *c1b    = (const float *)d_in[2];
    const float *d1w    = (const float *)d_in[3];
    const float *d1b    = (const float *)d_in[4];
    const float *d2w    = (const float *)d_in[5];
    const float *d2b    = (const float *)d_in[6];
    const float *d3w    = (const float *)d_in[7];
    const float *d3b    = (const float *)d_in[8];
    const float *pww    = (const float *)d_in[9];
    const float *pwb    = (const float *)d_in[10];
    const float *caw1   = (const float *)d_in[11];
    const float *caw2   = (const float *)d_in[12];
    const float *saw    = (const float *)d_in[13];
    const float *sab    = (const float *)d_in[14];
    const float *gng    = (const float *)d_in[15];
    const float *gnb    = (const float *)d_in[16];

    cudaFuncSetAttribute(k_main, cudaFuncAttributeMaxDynamicSharedMemorySize,
                         SMEM_BYTES);

    k_init<<<1, 512>>>();
    // nops so k_main is the 6th launch (ncu -s 5 -c 1 profiles k_main)
    k_nop1<<<1, 32>>>();
    k_nop2<<<1, 32>>>();
    k_nop3<<<1, 32>>>();
    k_nop4<<<1, 32>>>();
    k_main<<<dim3(16, 16, 8), NT, SMEM_BYTES>>>(
        x, c1w, c1b, d1w, d1b, d2w, d2b, d3w, d3b, pww, pwb);
    k_ca<<<8, 64>>>(caw1, caw2);
    k_sp<<<BB * HH, 256>>>();
    k_sa<<<dim3(16, 16, 8), dim3(16, 16)>>>(saw, sab);
    k_gnstats<<<dim3(16, 64, 8), 256>>>();
    k_fin<<<dim3(16, 64, 8), 256>>>((float *)d_out, gng, gnb);
}